// round 1
// baseline (speedup 1.0000x reference)
#include <cuda_runtime.h>
#include <math.h>

#define BATCH 2
#define SEQ   2048
#define DM    1024
#define NH    16
#define DK    64

// ---------------- scratch (device globals; no allocation allowed) ----------
__device__ float g_Q[BATCH * NH * SEQ * DK];   // [b,h,s,d]
__device__ float g_K[BATCH * NH * SEQ * DK];   // [b,h,s,d]
__device__ float g_V[BATCH * NH * SEQ * DK];   // [b,h,s,d]
__device__ float g_O[BATCH * SEQ * DM];        // [b,s,h*d] = [m, 1024]

// ---------------- SGEMM: 64x64 tile, BK=16, 256 threads, 4x4 per thread ----
#define GBM 64
#define GBN 64
#define GBK 16

__global__ __launch_bounds__(256) void gemm_qkv_kernel(
    const float* __restrict__ x,
    const float* __restrict__ WQ,
    const float* __restrict__ WK,
    const float* __restrict__ WV)
{
    __shared__ float As[GBK][GBM];
    __shared__ float Bs[GBK][GBN];

    const int z = blockIdx.z;
    const float* __restrict__ W = (z == 0) ? WQ : (z == 1) ? WK : WV;
    float* __restrict__ dst = (z == 0) ? g_Q : (z == 1) ? g_K : g_V;

    const int m0 = blockIdx.y * GBM;
    const int n0 = blockIdx.x * GBN;
    const int tid = threadIdx.x;
    const int tx = tid & 15;        // output col group
    const int ty = tid >> 4;        // output row group

    const int arow = tid >> 2, aq = tid & 3;    // A tile loader: 64 rows x 4 float4
    const int brow = tid >> 4, bq = tid & 15;   // B tile loader: 16 rows x 16 float4

    float acc[4][4] = {};

    for (int k0 = 0; k0 < DM; k0 += GBK) {
        float4 a4 = *(const float4*)(x + (size_t)(m0 + arow) * DM + k0 + aq * 4);
        As[aq * 4 + 0][arow] = a4.x;
        As[aq * 4 + 1][arow] = a4.y;
        As[aq * 4 + 2][arow] = a4.z;
        As[aq * 4 + 3][arow] = a4.w;
        *(float4*)(&Bs[brow][bq * 4]) =
            *(const float4*)(W + (size_t)(k0 + brow) * DM + n0 + bq * 4);
        __syncthreads();

        #pragma unroll
        for (int kk = 0; kk < GBK; kk++) {
            float4 av = *(const float4*)(&As[kk][ty * 4]);
            float4 bv = *(const float4*)(&Bs[kk][tx * 4]);
            float a[4] = {av.x, av.y, av.z, av.w};
            float b[4] = {bv.x, bv.y, bv.z, bv.w};
            #pragma unroll
            for (int r = 0; r < 4; r++)
                #pragma unroll
                for (int c = 0; c < 4; c++)
                    acc[r][c] += a[r] * b[c];
        }
        __syncthreads();
    }

    // scatter into [b,h,s,d]
    #pragma unroll
    for (int r = 0; r < 4; r++) {
        const int m = m0 + ty * 4 + r;
        const int b_ = m >> 11;          // / SEQ
        const int s_ = m & (SEQ - 1);
        #pragma unroll
        for (int c = 0; c < 4; c++) {
            const int n = n0 + tx * 4 + c;
            const int h = n >> 6, d = n & 63;
            dst[(((size_t)(b_ * NH + h)) * SEQ + s_) * DK + d] = acc[r][c];
        }
    }
}

__global__ __launch_bounds__(256) void gemm_out_kernel(
    const float* __restrict__ WO, float* __restrict__ out)
{
    __shared__ float As[GBK][GBM];
    __shared__ float Bs[GBK][GBN];

    const int m0 = blockIdx.y * GBM;
    const int n0 = blockIdx.x * GBN;
    const int tid = threadIdx.x;
    const int tx = tid & 15;
    const int ty = tid >> 4;
    const int arow = tid >> 2, aq = tid & 3;
    const int brow = tid >> 4, bq = tid & 15;

    float acc[4][4] = {};

    for (int k0 = 0; k0 < DM; k0 += GBK) {
        float4 a4 = *(const float4*)(g_O + (size_t)(m0 + arow) * DM + k0 + aq * 4);
        As[aq * 4 + 0][arow] = a4.x;
        As[aq * 4 + 1][arow] = a4.y;
        As[aq * 4 + 2][arow] = a4.z;
        As[aq * 4 + 3][arow] = a4.w;
        *(float4*)(&Bs[brow][bq * 4]) =
            *(const float4*)(WO + (size_t)(k0 + brow) * DM + n0 + bq * 4);
        __syncthreads();

        #pragma unroll
        for (int kk = 0; kk < GBK; kk++) {
            float4 av = *(const float4*)(&As[kk][ty * 4]);
            float4 bv = *(const float4*)(&Bs[kk][tx * 4]);
            float a[4] = {av.x, av.y, av.z, av.w};
            float b[4] = {bv.x, bv.y, bv.z, bv.w};
            #pragma unroll
            for (int r = 0; r < 4; r++)
                #pragma unroll
                for (int c = 0; c < 4; c++)
                    acc[r][c] += a[r] * b[c];
        }
        __syncthreads();
    }

    #pragma unroll
    for (int r = 0; r < 4; r++) {
        const int m = m0 + ty * 4 + r;
        #pragma unroll
        for (int c = 0; c < 4; c++) {
            const int n = n0 + tx * 4 + c;
            out[(size_t)m * DM + n] = acc[r][c];
        }
    }
}

// ---------------- RoPE on Q and K, [b,h,s,d] layout, pairs (2i, 2i+1) -------
__global__ void rope_kernel(const int* __restrict__ pos)
{
    const int NP = BATCH * NH * SEQ * (DK / 2);
    int idx = blockIdx.x * blockDim.x + threadIdx.x;
    if (idx >= NP) return;

    const int i  = idx & 31;                 // pair index within head dim
    const int s_ = (idx >> 5) & (SEQ - 1);   // sequence position
    const int bh = idx >> 16;                // / (32*SEQ)
    const int b_ = bh >> 4;                  // / NH

    const int p = pos[b_ * SEQ + s_];
    const float e = (float)(2 * i) / 64.0f;
    const float invf = 1.0f / powf(10000.0f, e);
    const float ang = (float)p * invf;
    float sn, cs;
    sincosf(ang, &sn, &cs);

    const size_t base = (size_t)idx * 2;
    float qe = g_Q[base], qo = g_Q[base + 1];
    g_Q[base]     = qe * cs - qo * sn;
    g_Q[base + 1] = qe * sn + qo * cs;
    float ke = g_K[base], ko = g_K[base + 1];
    g_K[base]     = ke * cs - ko * sn;
    g_K[base + 1] = ke * sn + ko * cs;
}

// ---------------- causal flash attention, fp32 ------------------------------
// One CTA = 128 query rows of one (b,h). One thread = one query row.
// q and o live entirely in registers -> online softmax has no reductions.
#define FM 128
#define FN 32

__global__ __launch_bounds__(128) void flash_kernel()
{
    __shared__ float Ks[FN][DK];
    __shared__ float Vs[FN][DK];

    const int bh = blockIdx.y;
    const int m0 = blockIdx.x * FM;
    const int tid = threadIdx.x;
    const int i = m0 + tid;                 // global query row (== seq pos)

    const float* __restrict__ Qp = g_Q + (size_t)bh * SEQ * DK + (size_t)i * DK;
    const float* __restrict__ Kb = g_K + (size_t)bh * SEQ * DK;
    const float* __restrict__ Vb = g_V + (size_t)bh * SEQ * DK;

    float4 q4[16];
    #pragma unroll
    for (int d = 0; d < 16; d++) q4[d] = *(const float4*)(Qp + d * 4);

    float4 o4[16];
    #pragma unroll
    for (int d = 0; d < 16; d++) o4[d] = make_float4(0.f, 0.f, 0.f, 0.f);

    float mval = -3e38f, l = 0.f;

    for (int j0 = 0; j0 < m0 + FM; j0 += FN) {
        // cooperative tile load: 512 float4 per tile, 128 threads x 4 iters
        #pragma unroll
        for (int it = 0; it < 4; it++) {
            const int idx = tid + it * 128;          // 0..511
            const int jj = idx >> 4, dq = idx & 15;
            *(float4*)(&Ks[jj][dq * 4]) =
                *(const float4*)(Kb + (size_t)(j0 + jj) * DK + dq * 4);
            *(float4*)(&Vs[jj][dq * 4]) =
                *(const float4*)(Vb + (size_t)(j0 + jj) * DK + dq * 4);
        }
        __syncthreads();

        float sreg[FN];
        #pragma unroll
        for (int jj = 0; jj < FN; jj++) {
            float acc = 0.f;
            #pragma unroll
            for (int d = 0; d < 16; d++) {
                float4 k4 = *(const float4*)(&Ks[jj][d * 4]);   // broadcast
                acc += q4[d].x * k4.x + q4[d].y * k4.y
                     + q4[d].z * k4.z + q4[d].w * k4.w;
            }
            sreg[jj] = (j0 + jj <= i) ? acc * 0.125f : -1e30f;
        }

        float mnew = mval;
        #pragma unroll
        for (int jj = 0; jj < FN; jj++) mnew = fmaxf(mnew, sreg[jj]);

        const float scale = __expf(mval - mnew);
        l *= scale;
        #pragma unroll
        for (int d = 0; d < 16; d++) {
            o4[d].x *= scale; o4[d].y *= scale;
            o4[d].z *= scale; o4[d].w *= scale;
        }

        #pragma unroll
        for (int jj = 0; jj < FN; jj++) {
            const float p = __expf(sreg[jj] - mnew);
            l += p;
            #pragma unroll
            for (int d = 0; d < 16; d++) {
                float4 v4 = *(const float4*)(&Vs[jj][d * 4]);   // broadcast
                o4[d].x += p * v4.x; o4[d].y += p * v4.y;
                o4[d].z += p * v4.z; o4[d].w += p * v4.w;
            }
        }
        mval = mnew;
        __syncthreads();
    }

    const float inv = 1.0f / l;
    const int b_ = bh >> 4, h = bh & 15;
    float* __restrict__ Op = g_O + (((size_t)(b_ * SEQ + i)) * NH + h) * DK;
    #pragma unroll
    for (int d = 0; d < 16; d++) {
        float4 w = o4[d];
        w.x *= inv; w.y *= inv; w.z *= inv; w.w *= inv;
        *(float4*)(Op + d * 4) = w;
    }
}

// ---------------- launch ----------------------------------------------------
extern "C" void kernel_launch(void* const* d_in, const int* in_sizes, int n_in,
                              void* d_out, int out_size)
{
    (void)in_sizes; (void)n_in; (void)out_size;
    const float* x   = (const float*)d_in[0];
    const int*   pos = (const int*)  d_in[1];
    const float* WQ  = (const float*)d_in[2];
    const float* WK  = (const float*)d_in[3];
    const float* WV  = (const float*)d_in[4];
    const float* WO  = (const float*)d_in[5];
    float* out = (float*)d_out;

    dim3 gq(DM / GBN, (BATCH * SEQ) / GBM, 3);
    gemm_qkv_kernel<<<gq, 256>>>(x, WQ, WK, WV);

    const int NP = BATCH * NH * SEQ * (DK / 2);
    rope_kernel<<<(NP + 255) / 256, 256>>>(pos);

    dim3 gf(SEQ / FM, BATCH * NH);
    flash_kernel<<<gf, 128>>>();

    dim3 go(DM / GBN, (BATCH * SEQ) / GBM);
    gemm_out_kernel<<<go, 256>>>(WO, out);
}

// round 3
// speedup vs baseline: 1.4530x; 1.4530x over previous
#include <cuda_runtime.h>
#include <math.h>
#include <stdint.h>

#define BATCH 2
#define SEQ   2048
#define DM    1024
#define NH    16
#define DK    64

// ---------------- scratch (device globals; no allocation allowed) ----------
__device__ float g_Q[BATCH * NH * SEQ * DK];   // [b,h,s,d]
__device__ float g_K[BATCH * NH * SEQ * DK];   // [b,h,s,d]
__device__ float g_V[BATCH * NH * SEQ * DK];   // [b,h,s,d]
__device__ float g_O[BATCH * SEQ * DM];        // [b,s,h*d]

// ---------------- tf32 MMA GEMM: 128x128x16 tiles, 8 warps ------------------
#define TBM 128
#define TBN 128
#define TBK 16
#define APAD 20
#define BPAD 136

__device__ __forceinline__ float to_tf32(float x) {
    float r;
    asm("cvt.rna.tf32.f32 %0, %1;" : "=f"(r) : "f"(x));
    return r;
}

__device__ __forceinline__ void mma_tf32(
    float& d0, float& d1, float& d2, float& d3,
    uint32_t a0, uint32_t a1, uint32_t a2, uint32_t a3,
    uint32_t b0, uint32_t b1)
{
    asm volatile(
        "mma.sync.aligned.m16n8k8.row.col.f32.tf32.tf32.f32 "
        "{%0,%1,%2,%3}, {%4,%5,%6,%7}, {%8,%9}, {%0,%1,%2,%3};\n"
        : "+f"(d0), "+f"(d1), "+f"(d2), "+f"(d3)
        : "r"(a0), "r"(a1), "r"(a2), "r"(a3), "r"(b0), "r"(b1));
}

// mode 0: A=Ain(x), W selected by blockIdx.z (WQ/WK/WV), dst = g_Q/g_K/g_V [b,h,s,d]
// mode 1: A=g_O (resolved IN KERNEL), W=W0, dst = out (row-major [4096][1024])
__global__ __launch_bounds__(256) void gemm_tf32_kernel(
    const float* __restrict__ Ain,
    const float* __restrict__ W0,
    const float* __restrict__ W1,
    const float* __restrict__ W2,
    float* __restrict__ out,
    int mode)
{
    __shared__ float As[2][TBM * APAD];
    __shared__ float Bs[2][TBK * BPAD];

    // CRITICAL: device-global scratch must be resolved in device code.
    const float* __restrict__ A = (mode == 1) ? (const float*)g_O : Ain;

    const int z = blockIdx.z;
    const float* __restrict__ W = (z == 0) ? W0 : (z == 1) ? W1 : W2;
    float* __restrict__ dstz = (mode == 1) ? out : (z == 0) ? g_Q : (z == 1) ? g_K : g_V;

    const int m0 = blockIdx.y * TBM;
    const int n0 = blockIdx.x * TBN;
    const int tid  = threadIdx.x;
    const int lane = tid & 31;
    const int wid  = tid >> 5;
    const int wm = wid >> 2;
    const int wn = wid & 3;
    const int lr = lane >> 2;
    const int lc = lane & 3;

    const int ar0 = tid >> 2;
    const int aq0 = tid & 3;
    const int br0 = tid >> 5;
    const int bq0 = tid & 31;

    float acc[4][4][4];
    #pragma unroll
    for (int i = 0; i < 4; i++)
        #pragma unroll
        for (int j = 0; j < 4; j++)
            #pragma unroll
            for (int r = 0; r < 4; r++) acc[i][j][r] = 0.f;

    {
        #pragma unroll
        for (int i = 0; i < 2; i++) {
            const int row = ar0 + i * 64, q = aq0;
            float4 v = *(const float4*)(A + (size_t)(m0 + row) * DM + q * 4);
            v.x = to_tf32(v.x); v.y = to_tf32(v.y); v.z = to_tf32(v.z); v.w = to_tf32(v.w);
            *(float4*)(&As[0][row * APAD + q * 4]) = v;
        }
        #pragma unroll
        for (int i = 0; i < 2; i++) {
            const int row = br0 + i * 8, q = bq0;
            float4 v = *(const float4*)(W + (size_t)row * DM + n0 + q * 4);
            v.x = to_tf32(v.x); v.y = to_tf32(v.y); v.z = to_tf32(v.z); v.w = to_tf32(v.w);
            *(float4*)(&Bs[0][row * BPAD + q * 4]) = v;
        }
    }
    __syncthreads();

    const int NT = DM / TBK;
    for (int kt = 0; kt < NT; kt++) {
        const int cur = kt & 1;
        float4 la[2], lb[2];
        const bool more = (kt + 1 < NT);
        if (more) {
            const int k0 = (kt + 1) * TBK;
            #pragma unroll
            for (int i = 0; i < 2; i++)
                la[i] = *(const float4*)(A + (size_t)(m0 + ar0 + i * 64) * DM + k0 + aq0 * 4);
            #pragma unroll
            for (int i = 0; i < 2; i++)
                lb[i] = *(const float4*)(W + (size_t)(k0 + br0 + i * 8) * DM + n0 + bq0 * 4);
        }

        const float* as = &As[cur][0];
        const float* bs = &Bs[cur][0];
        #pragma unroll
        for (int ks = 0; ks < 2; ks++) {
            const int k0 = ks * 8;
            uint32_t af[4][4], bf[4][2];
            #pragma unroll
            for (int mf = 0; mf < 4; mf++) {
                const int r = wm * 64 + mf * 16 + lr;
                af[mf][0] = __float_as_uint(as[(r    ) * APAD + k0 + lc    ]);
                af[mf][1] = __float_as_uint(as[(r + 8) * APAD + k0 + lc    ]);
                af[mf][2] = __float_as_uint(as[(r    ) * APAD + k0 + lc + 4]);
                af[mf][3] = __float_as_uint(as[(r + 8) * APAD + k0 + lc + 4]);
            }
            #pragma unroll
            for (int nf = 0; nf < 4; nf++) {
                const int c = wn * 32 + nf * 8 + lr;
                bf[nf][0] = __float_as_uint(bs[(k0 + lc    ) * BPAD + c]);
                bf[nf][1] = __float_as_uint(bs[(k0 + lc + 4) * BPAD + c]);
            }
            #pragma unroll
            for (int mf = 0; mf < 4; mf++)
                #pragma unroll
                for (int nf = 0; nf < 4; nf++)
                    mma_tf32(acc[mf][nf][0], acc[mf][nf][1], acc[mf][nf][2], acc[mf][nf][3],
                             af[mf][0], af[mf][1], af[mf][2], af[mf][3],
                             bf[nf][0], bf[nf][1]);
        }

        if (more) {
            const int nxt = cur ^ 1;
            #pragma unroll
            for (int i = 0; i < 2; i++) {
                float4 v = la[i];
                v.x = to_tf32(v.x); v.y = to_tf32(v.y); v.z = to_tf32(v.z); v.w = to_tf32(v.w);
                *(float4*)(&As[nxt][(ar0 + i * 64) * APAD + aq0 * 4]) = v;
            }
            #pragma unroll
            for (int i = 0; i < 2; i++) {
                float4 v = lb[i];
                v.x = to_tf32(v.x); v.y = to_tf32(v.y); v.z = to_tf32(v.z); v.w = to_tf32(v.w);
                *(float4*)(&Bs[nxt][(br0 + i * 8) * BPAD + bq0 * 4]) = v;
            }
        }
        __syncthreads();
    }

    const int rb = m0 + wm * 64 + lr;
    const int cb = n0 + wn * 32 + 2 * lc;
    #pragma unroll
    for (int mf = 0; mf < 4; mf++) {
        #pragma unroll
        for (int nf = 0; nf < 4; nf++) {
            const int n = cb + nf * 8;
            #pragma unroll
            for (int half = 0; half < 2; half++) {
                const int m = rb + mf * 16 + half * 8;
                float2 v = make_float2(acc[mf][nf][half * 2], acc[mf][nf][half * 2 + 1]);
                if (mode == 1) {
                    *(float2*)(out + (size_t)m * DM + n) = v;
                } else {
                    const int b_ = m >> 11, s_ = m & (SEQ - 1);
                    const int h = n >> 6, d = n & 63;
                    *(float2*)(dstz + (((size_t)(b_ * NH + h)) * SEQ + s_) * DK + d) = v;
                }
            }
        }
    }
}

// ---------------- RoPE on Q and K, [b,h,s,d] layout, pairs (2i, 2i+1) -------
__global__ void rope_kernel(const int* __restrict__ pos)
{
    const int NP = BATCH * NH * SEQ * (DK / 2);
    int idx = blockIdx.x * blockDim.x + threadIdx.x;
    if (idx >= NP) return;

    const int i  = idx & 31;
    const int s_ = (idx >> 5) & (SEQ - 1);
    const int bh = idx >> 16;
    const int b_ = bh >> 4;

    const int p = pos[b_ * SEQ + s_];
    const float e = (float)(2 * i) / 64.0f;
    const float invf = 1.0f / powf(10000.0f, e);
    const float ang = (float)p * invf;
    float sn, cs;
    sincosf(ang, &sn, &cs);

    const size_t base = (size_t)idx * 2;
    float qe = g_Q[base], qo = g_Q[base + 1];
    g_Q[base]     = qe * cs - qo * sn;
    g_Q[base + 1] = qe * sn + qo * cs;
    float ke = g_K[base], ko = g_K[base + 1];
    g_K[base]     = ke * cs - ko * sn;
    g_K[base + 1] = ke * sn + ko * cs;
}

// ---------------- causal flash attention, fp32 ------------------------------
#define FM 128
#define FN 32

__global__ __launch_bounds__(128) void flash_kernel()
{
    __shared__ float Ks[FN][DK];
    __shared__ float Vs[FN][DK];

    const int bh = blockIdx.y;
    const int m0 = blockIdx.x * FM;
    const int tid = threadIdx.x;
    const int i = m0 + tid;

    const float* __restrict__ Qp = g_Q + (size_t)bh * SEQ * DK + (size_t)i * DK;
    const float* __restrict__ Kb = g_K + (size_t)bh * SEQ * DK;
    const float* __restrict__ Vb = g_V + (size_t)bh * SEQ * DK;

    float4 q4[16];
    #pragma unroll
    for (int d = 0; d < 16; d++) q4[d] = *(const float4*)(Qp + d * 4);

    float4 o4[16];
    #pragma unroll
    for (int d = 0; d < 16; d++) o4[d] = make_float4(0.f, 0.f, 0.f, 0.f);

    float mval = -3e38f, l = 0.f;

    for (int j0 = 0; j0 < m0 + FM; j0 += FN) {
        #pragma unroll
        for (int it = 0; it < 4; it++) {
            const int idx = tid + it * 128;
            const int jj = idx >> 4, dq = idx & 15;
            *(float4*)(&Ks[jj][dq * 4]) =
                *(const float4*)(Kb + (size_t)(j0 + jj) * DK + dq * 4);
            *(float4*)(&Vs[jj][dq * 4]) =
                *(const float4*)(Vb + (size_t)(j0 + jj) * DK + dq * 4);
        }
        __syncthreads();

        float sreg[FN];
        #pragma unroll
        for (int jj = 0; jj < FN; jj++) {
            float acc = 0.f;
            #pragma unroll
            for (int d = 0; d < 16; d++) {
                float4 k4 = *(const float4*)(&Ks[jj][d * 4]);
                acc += q4[d].x * k4.x + q4[d].y * k4.y
                     + q4[d].z * k4.z + q4[d].w * k4.w;
            }
            sreg[jj] = (j0 + jj <= i) ? acc * 0.125f : -1e30f;
        }

        float mnew = mval;
        #pragma unroll
        for (int jj = 0; jj < FN; jj++) mnew = fmaxf(mnew, sreg[jj]);

        const float scale = __expf(mval - mnew);
        l *= scale;
        #pragma unroll
        for (int d = 0; d < 16; d++) {
            o4[d].x *= scale; o4[d].y *= scale;
            o4[d].z *= scale; o4[d].w *= scale;
        }

        #pragma unroll
        for (int jj = 0; jj < FN; jj++) {
            const float p = __expf(sreg[jj] - mnew);
            l += p;
            #pragma unroll
            for (int d = 0; d < 16; d++) {
                float4 v4 = *(const float4*)(&Vs[jj][d * 4]);
                o4[d].x += p * v4.x; o4[d].y += p * v4.y;
                o4[d].z += p * v4.z; o4[d].w += p * v4.w;
            }
        }
        mval = mnew;
        __syncthreads();
    }

    const float inv = 1.0f / l;
    const int b_ = bh >> 4, h = bh & 15;
    float* __restrict__ Op = g_O + (((size_t)(b_ * SEQ + i)) * NH + h) * DK;
    #pragma unroll
    for (int d = 0; d < 16; d++) {
        float4 w = o4[d];
        w.x *= inv; w.y *= inv; w.z *= inv; w.w *= inv;
        *(float4*)(Op + d * 4) = w;
    }
}

// ---------------- launch ----------------------------------------------------
extern "C" void kernel_launch(void* const* d_in, const int* in_sizes, int n_in,
                              void* d_out, int out_size)
{
    (void)in_sizes; (void)n_in; (void)out_size;
    const float* x   = (const float*)d_in[0];
    const int*   pos = (const int*)  d_in[1];
    const float* WQ  = (const float*)d_in[2];
    const float* WK  = (const float*)d_in[3];
    const float* WV  = (const float*)d_in[4];
    const float* WO  = (const float*)d_in[5];
    float* out = (float*)d_out;

    dim3 gq(DM / TBN, (BATCH * SEQ) / TBM, 3);
    gemm_tf32_kernel<<<gq, 256>>>(x, WQ, WK, WV, nullptr, 0);

    const int NP = BATCH * NH * SEQ * (DK / 2);
    rope_kernel<<<(NP + 255) / 256, 256>>>(pos);

    dim3 gf(SEQ / FM, BATCH * NH);
    flash_kernel<<<gf, 128>>>();

    dim3 go(DM / TBN, (BATCH * SEQ) / TBM, 1);
    gemm_tf32_kernel<<<go, 256>>>(nullptr, WO, nullptr, nullptr, out, 1);
}

// round 4
// speedup vs baseline: 4.1475x; 2.8544x over previous
#include <cuda_runtime.h>
#include <math.h>
#include <stdint.h>

#define BATCH 2
#define SEQ   2048
#define DM    1024
#define NH    16
#define DK    64

__device__ float g_Q[BATCH * NH * SEQ * DK];   // [b,h,s,d]
__device__ float g_K[BATCH * NH * SEQ * DK];   // [b,h,s,d]
__device__ float g_V[BATCH * NH * SEQ * DK];   // [b,h,s,d]
__device__ float g_O[BATCH * SEQ * DM];        // [b,s,h*d]

__device__ __forceinline__ float to_tf32(float x) {
    float r;
    asm("cvt.rna.tf32.f32 %0, %1;" : "=f"(r) : "f"(x));
    return r;
}

__device__ __forceinline__ void mma_tf32(
    float& d0, float& d1, float& d2, float& d3,
    uint32_t a0, uint32_t a1, uint32_t a2, uint32_t a3,
    uint32_t b0, uint32_t b1)
{
    asm volatile(
        "mma.sync.aligned.m16n8k8.row.col.f32.tf32.tf32.f32 "
        "{%0,%1,%2,%3}, {%4,%5,%6,%7}, {%8,%9}, {%0,%1,%2,%3};\n"
        : "+f"(d0), "+f"(d1), "+f"(d2), "+f"(d3)
        : "r"(a0), "r"(a1), "r"(a2), "r"(a3), "r"(b0), "r"(b1));
}

// ---------------- tf32 MMA GEMM (unchanged from R3) -------------------------
#define TBM 128
#define TBN 128
#define TBK 16
#define APAD 20
#define BPAD 136

__global__ __launch_bounds__(256) void gemm_tf32_kernel(
    const float* __restrict__ Ain,
    const float* __restrict__ W0,
    const float* __restrict__ W1,
    const float* __restrict__ W2,
    float* __restrict__ out,
    int mode)
{
    __shared__ float As[2][TBM * APAD];
    __shared__ float Bs[2][TBK * BPAD];

    const float* __restrict__ A = (mode == 1) ? (const float*)g_O : Ain;

    const int z = blockIdx.z;
    const float* __restrict__ W = (z == 0) ? W0 : (z == 1) ? W1 : W2;
    float* __restrict__ dstz = (mode == 1) ? out : (z == 0) ? g_Q : (z == 1) ? g_K : g_V;

    const int m0 = blockIdx.y * TBM;
    const int n0 = blockIdx.x * TBN;
    const int tid  = threadIdx.x;
    const int lane = tid & 31;
    const int wid  = tid >> 5;
    const int wm = wid >> 2;
    const int wn = wid & 3;
    const int lr = lane >> 2;
    const int lc = lane & 3;

    const int ar0 = tid >> 2;
    const int aq0 = tid & 3;
    const int br0 = tid >> 5;
    const int bq0 = tid & 31;

    float acc[4][4][4];
    #pragma unroll
    for (int i = 0; i < 4; i++)
        #pragma unroll
        for (int j = 0; j < 4; j++)
            #pragma unroll
            for (int r = 0; r < 4; r++) acc[i][j][r] = 0.f;

    {
        #pragma unroll
        for (int i = 0; i < 2; i++) {
            const int row = ar0 + i * 64, q = aq0;
            float4 v = *(const float4*)(A + (size_t)(m0 + row) * DM + q * 4);
            v.x = to_tf32(v.x); v.y = to_tf32(v.y); v.z = to_tf32(v.z); v.w = to_tf32(v.w);
            *(float4*)(&As[0][row * APAD + q * 4]) = v;
        }
        #pragma unroll
        for (int i = 0; i < 2; i++) {
            const int row = br0 + i * 8, q = bq0;
            float4 v = *(const float4*)(W + (size_t)row * DM + n0 + q * 4);
            v.x = to_tf32(v.x); v.y = to_tf32(v.y); v.z = to_tf32(v.z); v.w = to_tf32(v.w);
            *(float4*)(&Bs[0][row * BPAD + q * 4]) = v;
        }
    }
    __syncthreads();

    const int NT = DM / TBK;
    for (int kt = 0; kt < NT; kt++) {
        const int cur = kt & 1;
        float4 la[2], lb[2];
        const bool more = (kt + 1 < NT);
        if (more) {
            const int k0 = (kt + 1) * TBK;
            #pragma unroll
            for (int i = 0; i < 2; i++)
                la[i] = *(const float4*)(A + (size_t)(m0 + ar0 + i * 64) * DM + k0 + aq0 * 4);
            #pragma unroll
            for (int i = 0; i < 2; i++)
                lb[i] = *(const float4*)(W + (size_t)(k0 + br0 + i * 8) * DM + n0 + bq0 * 4);
        }

        const float* as = &As[cur][0];
        const float* bs = &Bs[cur][0];
        #pragma unroll
        for (int ks = 0; ks < 2; ks++) {
            const int k0 = ks * 8;
            uint32_t af[4][4], bf[4][2];
            #pragma unroll
            for (int mf = 0; mf < 4; mf++) {
                const int r = wm * 64 + mf * 16 + lr;
                af[mf][0] = __float_as_uint(as[(r    ) * APAD + k0 + lc    ]);
                af[mf][1] = __float_as_uint(as[(r + 8) * APAD + k0 + lc    ]);
                af[mf][2] = __float_as_uint(as[(r    ) * APAD + k0 + lc + 4]);
                af[mf][3] = __float_as_uint(as[(r + 8) * APAD + k0 + lc + 4]);
            }
            #pragma unroll
            for (int nf = 0; nf < 4; nf++) {
                const int c = wn * 32 + nf * 8 + lr;
                bf[nf][0] = __float_as_uint(bs[(k0 + lc    ) * BPAD + c]);
                bf[nf][1] = __float_as_uint(bs[(k0 + lc + 4) * BPAD + c]);
            }
            #pragma unroll
            for (int mf = 0; mf < 4; mf++)
                #pragma unroll
                for (int nf = 0; nf < 4; nf++)
                    mma_tf32(acc[mf][nf][0], acc[mf][nf][1], acc[mf][nf][2], acc[mf][nf][3],
                             af[mf][0], af[mf][1], af[mf][2], af[mf][3],
                             bf[nf][0], bf[nf][1]);
        }

        if (more) {
            const int nxt = cur ^ 1;
            #pragma unroll
            for (int i = 0; i < 2; i++) {
                float4 v = la[i];
                v.x = to_tf32(v.x); v.y = to_tf32(v.y); v.z = to_tf32(v.z); v.w = to_tf32(v.w);
                *(float4*)(&As[nxt][(ar0 + i * 64) * APAD + aq0 * 4]) = v;
            }
            #pragma unroll
            for (int i = 0; i < 2; i++) {
                float4 v = lb[i];
                v.x = to_tf32(v.x); v.y = to_tf32(v.y); v.z = to_tf32(v.z); v.w = to_tf32(v.w);
                *(float4*)(&Bs[nxt][(br0 + i * 8) * BPAD + bq0 * 4]) = v;
            }
        }
        __syncthreads();
    }

    const int rb = m0 + wm * 64 + lr;
    const int cb = n0 + wn * 32 + 2 * lc;
    #pragma unroll
    for (int mf = 0; mf < 4; mf++) {
        #pragma unroll
        for (int nf = 0; nf < 4; nf++) {
            const int n = cb + nf * 8;
            #pragma unroll
            for (int half = 0; half < 2; half++) {
                const int m = rb + mf * 16 + half * 8;
                float2 v = make_float2(acc[mf][nf][half * 2], acc[mf][nf][half * 2 + 1]);
                if (mode == 1) {
                    *(float2*)(out + (size_t)m * DM + n) = v;
                } else {
                    const int b_ = m >> 11, s_ = m & (SEQ - 1);
                    const int h = n >> 6, d = n & 63;
                    *(float2*)(dstz + (((size_t)(b_ * NH + h)) * SEQ + s_) * DK + d) = v;
                }
            }
        }
    }
}

// ---------------- RoPE (unchanged) ------------------------------------------
__global__ void rope_kernel(const int* __restrict__ pos)
{
    const int NP = BATCH * NH * SEQ * (DK / 2);
    int idx = blockIdx.x * blockDim.x + threadIdx.x;
    if (idx >= NP) return;

    const int i  = idx & 31;
    const int s_ = (idx >> 5) & (SEQ - 1);
    const int bh = idx >> 16;
    const int b_ = bh >> 4;

    const int p = pos[b_ * SEQ + s_];
    const float e = (float)(2 * i) / 64.0f;
    const float invf = 1.0f / powf(10000.0f, e);
    const float ang = (float)p * invf;
    float sn, cs;
    sincosf(ang, &sn, &cs);

    const size_t base = (size_t)idx * 2;
    float qe = g_Q[base], qo = g_Q[base + 1];
    g_Q[base]     = qe * cs - qo * sn;
    g_Q[base + 1] = qe * sn + qo * cs;
    float ke = g_K[base], ko = g_K[base + 1];
    g_K[base]     = ke * cs - ko * sn;
    g_K[base + 1] = ke * sn + ko * cs;
}

// ---------------- tf32 MMA flash attention ----------------------------------
// CTA = 64 query rows, 4 warps x 16 rows. KV tile = 64. Causal.
#define FBM 64
#define FBN 64
#define KP  68   // K smem pad: b-frag banks = 4*lr+lc (distinct)
#define VP  72   // V smem pad: b-frag banks = 8*j+d   (distinct)
#define PP  68   // P/Q smem pad: a-frag banks = 4*lr+lc (distinct)
#define FLASH_SMEM ((64*KP + 64*VP + 64*PP) * 4)

__global__ __launch_bounds__(128) void flash_mma_kernel()
{
    extern __shared__ float fsm[];
    float* Ks = fsm;                    // [64][KP]
    float* Vs = fsm + 64 * KP;          // [64][VP]
    float* Ps = fsm + 64 * (KP + VP);   // [64][PP], warp w owns rows 16w..16w+15

    const int bh = blockIdx.y;
    const int m0 = ((int)gridDim.x - 1 - (int)blockIdx.x) * FBM;  // heavy blocks first
    const int tid  = threadIdx.x;
    const int lane = tid & 31;
    const int w    = tid >> 5;
    const int lr   = lane >> 2;
    const int lc   = lane & 3;

    const float* __restrict__ Qb = g_Q + (size_t)bh * SEQ * DK;
    const float* __restrict__ Kb = g_K + (size_t)bh * SEQ * DK;
    const float* __restrict__ Vb = g_V + (size_t)bh * SEQ * DK;

    // ---- stage Q (x 1/sqrt(64), tf32) through Ps, then to register frags ----
    #pragma unroll
    for (int it = 0; it < 8; it++) {
        const int idx = tid + it * 128;       // 0..1023
        const int row = idx >> 4, q = idx & 15;
        float4 v = *(const float4*)(Qb + (size_t)(m0 + row) * DK + q * 4);
        v.x = to_tf32(v.x * 0.125f); v.y = to_tf32(v.y * 0.125f);
        v.z = to_tf32(v.z * 0.125f); v.w = to_tf32(v.w * 0.125f);
        *(float4*)(Ps + row * PP + q * 4) = v;
    }
    __syncthreads();

    uint32_t qf[8][4];
    {
        const float* Pq = Ps + (w * 16) * PP;
        #pragma unroll
        for (int k = 0; k < 8; k++) {
            qf[k][0] = __float_as_uint(Pq[(lr    ) * PP + k * 8 + lc    ]);
            qf[k][1] = __float_as_uint(Pq[(lr + 8) * PP + k * 8 + lc    ]);
            qf[k][2] = __float_as_uint(Pq[(lr    ) * PP + k * 8 + lc + 4]);
            qf[k][3] = __float_as_uint(Pq[(lr + 8) * PP + k * 8 + lc + 4]);
        }
    }

    float o[8][4];
    #pragma unroll
    for (int n = 0; n < 8; n++)
        #pragma unroll
        for (int c = 0; c < 4; c++) o[n][c] = 0.f;
    float mrow0 = -1e30f, mrow1 = -1e30f, lrow0 = 0.f, lrow1 = 0.f;

    const int nt = m0 / FBN + 1;
    for (int t = 0; t < nt; t++) {
        const int j0 = t * FBN;
        __syncthreads();   // protect Ks/Vs/Ps from previous iter (and Q staging)
        #pragma unroll
        for (int it = 0; it < 8; it++) {
            const int idx = tid + it * 128;
            const int row = idx >> 4, q = idx & 15;
            float4 kv = *(const float4*)(Kb + (size_t)(j0 + row) * DK + q * 4);
            kv.x = to_tf32(kv.x); kv.y = to_tf32(kv.y);
            kv.z = to_tf32(kv.z); kv.w = to_tf32(kv.w);
            *(float4*)(Ks + row * KP + q * 4) = kv;
            float4 vv = *(const float4*)(Vb + (size_t)(j0 + row) * DK + q * 4);
            vv.x = to_tf32(vv.x); vv.y = to_tf32(vv.y);
            vv.z = to_tf32(vv.z); vv.w = to_tf32(vv.w);
            *(float4*)(Vs + row * VP + q * 4) = vv;
        }
        __syncthreads();

        // ---- S = Q K^T (rows w*16..w*16+15, cols 0..63) ----
        float s[8][4];
        #pragma unroll
        for (int n = 0; n < 8; n++)
            #pragma unroll
            for (int c = 0; c < 4; c++) s[n][c] = 0.f;

        #pragma unroll
        for (int k = 0; k < 8; k++) {
            #pragma unroll
            for (int n = 0; n < 8; n++) {
                const uint32_t b0 = __float_as_uint(Ks[(n * 8 + lr) * KP + k * 8 + lc    ]);
                const uint32_t b1 = __float_as_uint(Ks[(n * 8 + lr) * KP + k * 8 + lc + 4]);
                mma_tf32(s[n][0], s[n][1], s[n][2], s[n][3],
                         qf[k][0], qf[k][1], qf[k][2], qf[k][3], b0, b1);
            }
        }

        // ---- causal mask: only the diagonal tile (j0 == m0) needs it ----
        if (t == nt - 1) {
            const int r0 = w * 16 + lr;
            #pragma unroll
            for (int n = 0; n < 8; n++) {
                const int c0 = n * 8 + 2 * lc;
                if (c0     > r0)     s[n][0] = -1e30f;
                if (c0 + 1 > r0)     s[n][1] = -1e30f;
                if (c0     > r0 + 8) s[n][2] = -1e30f;
                if (c0 + 1 > r0 + 8) s[n][3] = -1e30f;
            }
        }

        // ---- online softmax (rows lr and lr+8) ----
        float mx0 = -1e30f, mx1 = -1e30f;
        #pragma unroll
        for (int n = 0; n < 8; n++) {
            mx0 = fmaxf(mx0, fmaxf(s[n][0], s[n][1]));
            mx1 = fmaxf(mx1, fmaxf(s[n][2], s[n][3]));
        }
        mx0 = fmaxf(mx0, __shfl_xor_sync(0xffffffffu, mx0, 1));
        mx0 = fmaxf(mx0, __shfl_xor_sync(0xffffffffu, mx0, 2));
        mx1 = fmaxf(mx1, __shfl_xor_sync(0xffffffffu, mx1, 1));
        mx1 = fmaxf(mx1, __shfl_xor_sync(0xffffffffu, mx1, 2));

        const float mn0 = fmaxf(mrow0, mx0);
        const float mn1 = fmaxf(mrow1, mx1);
        const float sc0 = __expf(mrow0 - mn0);
        const float sc1 = __expf(mrow1 - mn1);
        lrow0 *= sc0; lrow1 *= sc1;
        #pragma unroll
        for (int n = 0; n < 8; n++) {
            o[n][0] *= sc0; o[n][1] *= sc0;
            o[n][2] *= sc1; o[n][3] *= sc1;
        }
        mrow0 = mn0; mrow1 = mn1;

        float* Pw = Ps + (w * 16) * PP;
        #pragma unroll
        for (int n = 0; n < 8; n++) {
            const float p0 = __expf(s[n][0] - mn0);
            const float p1 = __expf(s[n][1] - mn0);
            const float p2 = __expf(s[n][2] - mn1);
            const float p3 = __expf(s[n][3] - mn1);
            lrow0 += p0 + p1;
            lrow1 += p2 + p3;
            *(float2*)(Pw + (lr    ) * PP + n * 8 + 2 * lc) = make_float2(to_tf32(p0), to_tf32(p1));
            *(float2*)(Pw + (lr + 8) * PP + n * 8 + 2 * lc) = make_float2(to_tf32(p2), to_tf32(p3));
        }
        __syncwarp();

        // ---- O += P V ----
        #pragma unroll
        for (int k = 0; k < 8; k++) {
            const uint32_t a0 = __float_as_uint(Pw[(lr    ) * PP + k * 8 + lc    ]);
            const uint32_t a1 = __float_as_uint(Pw[(lr + 8) * PP + k * 8 + lc    ]);
            const uint32_t a2 = __float_as_uint(Pw[(lr    ) * PP + k * 8 + lc + 4]);
            const uint32_t a3 = __float_as_uint(Pw[(lr + 8) * PP + k * 8 + lc + 4]);
            #pragma unroll
            for (int n = 0; n < 8; n++) {
                const uint32_t b0 = __float_as_uint(Vs[(k * 8 + lc    ) * VP + n * 8 + lr]);
                const uint32_t b1 = __float_as_uint(Vs[(k * 8 + lc + 4) * VP + n * 8 + lr]);
                mma_tf32(o[n][0], o[n][1], o[n][2], o[n][3], a0, a1, a2, a3, b0, b1);
            }
        }
    }

    // ---- finalize: reduce l across quad, normalize, write g_O [b,s,h*d] ----
    lrow0 += __shfl_xor_sync(0xffffffffu, lrow0, 1);
    lrow0 += __shfl_xor_sync(0xffffffffu, lrow0, 2);
    lrow1 += __shfl_xor_sync(0xffffffffu, lrow1, 1);
    lrow1 += __shfl_xor_sync(0xffffffffu, lrow1, 2);
    const float inv0 = 1.0f / lrow0;
    const float inv1 = 1.0f / lrow1;

    const int b_ = bh >> 4, h = bh & 15;
    const int r0 = m0 + w * 16 + lr;
    const int r1 = r0 + 8;
    #pragma unroll
    for (int n = 0; n < 8; n++) {
        const int d = h * 64 + n * 8 + 2 * lc;
        *(float2*)(g_O + ((size_t)b_ * SEQ + r0) * DM + d) =
            make_float2(o[n][0] * inv0, o[n][1] * inv0);
        *(float2*)(g_O + ((size_t)b_ * SEQ + r1) * DM + d) =
            make_float2(o[n][2] * inv1, o[n][3] * inv1);
    }
}

// ---------------- launch ----------------------------------------------------
extern "C" void kernel_launch(void* const* d_in, const int* in_sizes, int n_in,
                              void* d_out, int out_size)
{
    (void)in_sizes; (void)n_in; (void)out_size;
    const float* x   = (const float*)d_in[0];
    const int*   pos = (const int*)  d_in[1];
    const float* WQ  = (const float*)d_in[2];
    const float* WK  = (const float*)d_in[3];
    const float* WV  = (const float*)d_in[4];
    const float* WO  = (const float*)d_in[5];
    float* out = (float*)d_out;

    cudaFuncSetAttribute(flash_mma_kernel,
                         cudaFuncAttributeMaxDynamicSharedMemorySize, FLASH_SMEM);

    dim3 gq(DM / TBN, (BATCH * SEQ) / TBM, 3);
    gemm_tf32_kernel<<<gq, 256>>>(x, WQ, WK, WV, nullptr, 0);

    const int NP = BATCH * NH * SEQ * (DK / 2);
    rope_kernel<<<(NP + 255) / 256, 256>>>(pos);

    dim3 gf(SEQ / FBM, BATCH * NH);
    flash_mma_kernel<<<gf, 128, FLASH_SMEM>>>();

    dim3 go(DM / TBN, (BATCH * SEQ) / TBM, 1);
    gemm_tf32_kernel<<<go, 256>>>(nullptr, WO, nullptr, nullptr, out, 1);
}